// round 4
// baseline (speedup 1.0000x reference)
#include <cuda_runtime.h>
#include <cuda_bf16.h>
#include <math.h>

// Batched Kabsch RMSD:
//  K1: persistent fine-grained streaming. Job = quarter-batch (512 points).
//      grid = 148*5 CTAs, static strided jobs per warp, warp-local reduce,
//      writes 17 scalars per job.
//  K2: per-batch: sum 4 quarter-partials, fp32 closed-form 3x3 eigensolve,
//      per-CTA rmsd partial sum.
//  K3: tiny final mean.

#define NPTS     2048
#define BATCHES  4096
#define JOBS     (BATCHES * 4)          // quarter-batches
#define NCTA     740                    // 148 SMs * 5 resident CTAs
#define NWARP    (NCTA * 8)
#define K2_BLOCK 256

__device__ float g_part4[JOBS * 17];
__device__ float g_psum[BATCHES / K2_BLOCK];

__device__ __forceinline__ float warp_sum(float v) {
    #pragma unroll
    for (int o = 16; o > 0; o >>= 1)
        v += __shfl_down_sync(0xffffffffu, v, o);
    return v;
}

__device__ __forceinline__ float4 ldcs4(const float4* p) {
    return __ldcs(p);
}

// ---------------- K1: persistent streaming ----------------
__global__ __launch_bounds__(256, 5)
void stream_kernel(const float* __restrict__ P,
                   const float* __restrict__ Q)
{
    const int lane  = threadIdx.x & 31;
    const int wid   = threadIdx.x >> 5;
    const int gwarp = blockIdx.x * 8 + wid;

    for (int jid = gwarp; jid < JOBS; jid += NWARP) {
        const int b = jid >> 2;
        const int q = jid & 3;

        const float4* pb = reinterpret_cast<const float4*>(P + (size_t)b * (NPTS * 3));
        const float4* qb = reinterpret_cast<const float4*>(Q + (size_t)b * (NPTS * 3));

        // acc: [0..2]=sum_p, [3..5]=sum_q, [6]=sum|p|^2, [7]=sum|q|^2,
        //      [8..16]=sum p_a*q_b (row-major)
        float acc[17];
        #pragma unroll
        for (int i = 0; i < 17; i++) acc[i] = 0.f;

        #pragma unroll
        for (int it = 0; it < 4; it++) {
            const int g = q * 128 + it * 32 + lane;   // group of 4 points
            float4 pA = ldcs4(&pb[3*g+0]);
            float4 pB = ldcs4(&pb[3*g+1]);
            float4 pC = ldcs4(&pb[3*g+2]);
            float4 qA = ldcs4(&qb[3*g+0]);
            float4 qB = ldcs4(&qb[3*g+1]);
            float4 qC = ldcs4(&qb[3*g+2]);

            float px[4] = {pA.x, pA.w, pB.z, pC.y};
            float py[4] = {pA.y, pB.x, pB.w, pC.z};
            float pz[4] = {pA.z, pB.y, pC.x, pC.w};
            float qx[4] = {qA.x, qA.w, qB.z, qC.y};
            float qy[4] = {qA.y, qB.x, qB.w, qC.z};
            float qz[4] = {qA.z, qB.y, qC.x, qC.w};

            #pragma unroll
            for (int k = 0; k < 4; k++) {
                acc[0] += px[k]; acc[1] += py[k]; acc[2] += pz[k];
                acc[3] += qx[k]; acc[4] += qy[k]; acc[5] += qz[k];
                acc[6]  = fmaf(px[k], px[k], fmaf(py[k], py[k], fmaf(pz[k], pz[k], acc[6])));
                acc[7]  = fmaf(qx[k], qx[k], fmaf(qy[k], qy[k], fmaf(qz[k], qz[k], acc[7])));
                acc[8]  = fmaf(px[k], qx[k], acc[8]);
                acc[9]  = fmaf(px[k], qy[k], acc[9]);
                acc[10] = fmaf(px[k], qz[k], acc[10]);
                acc[11] = fmaf(py[k], qx[k], acc[11]);
                acc[12] = fmaf(py[k], qy[k], acc[12]);
                acc[13] = fmaf(py[k], qz[k], acc[13]);
                acc[14] = fmaf(pz[k], qx[k], acc[14]);
                acc[15] = fmaf(pz[k], qy[k], acc[15]);
                acc[16] = fmaf(pz[k], qz[k], acc[16]);
            }
        }

        #pragma unroll
        for (int i = 0; i < 17; i++) {
            float v = warp_sum(acc[i]);
            if (lane == 0) g_part4[jid * 17 + i] = v;
        }
    }
}

// ---------------- K2: combine quarters + fp32 eigensolve ----------------
__global__ __launch_bounds__(K2_BLOCK)
void solve_kernel(void)
{
    const int b = blockIdx.x * blockDim.x + threadIdx.x;

    float fin[17];
    {
        const float* base = &g_part4[(size_t)b * 4 * 17];
        #pragma unroll
        for (int i = 0; i < 17; i++)
            fin[i] = (base[i] + base[17 + i]) + (base[34 + i] + base[51 + i]);
    }

    const float n = (float)NPTS;
    const float invn = 1.0f / n;
    float pm0 = fin[0] * invn, pm1 = fin[1] * invn, pm2 = fin[2] * invn;
    float qm0 = fin[3] * invn, qm1 = fin[4] * invn, qm2 = fin[5] * invn;
    float Ep = fin[6] - n * (pm0*pm0 + pm1*pm1 + pm2*pm2);
    float Ec = fin[7] - n * (qm0*qm0 + qm1*qm1 + qm2*qm2);

    float A0 = fin[8]  - n * pm0 * qm0;
    float A1 = fin[9]  - n * pm0 * qm1;
    float A2 = fin[10] - n * pm0 * qm2;
    float A3 = fin[11] - n * pm1 * qm0;
    float A4 = fin[12] - n * pm1 * qm1;
    float A5 = fin[13] - n * pm1 * qm2;
    float A6 = fin[14] - n * pm2 * qm0;
    float A7 = fin[15] - n * pm2 * qm1;
    float A8 = fin[16] - n * pm2 * qm2;

    float detA = A0 * (A4 * A8 - A5 * A7)
               - A1 * (A3 * A8 - A5 * A6)
               + A2 * (A3 * A7 - A4 * A6);

    float m00 = A0*A0 + A3*A3 + A6*A6;
    float m01 = A0*A1 + A3*A4 + A6*A7;
    float m02 = A0*A2 + A3*A5 + A6*A8;
    float m11 = A1*A1 + A4*A4 + A7*A7;
    float m12 = A1*A2 + A4*A5 + A7*A8;
    float m22 = A2*A2 + A5*A5 + A8*A8;

    float q  = (m00 + m11 + m22) * (1.0f/3.0f);
    float p1 = m01*m01 + m02*m02 + m12*m12;
    float p2 = (m00-q)*(m00-q) + (m11-q)*(m11-q) + (m22-q)*(m22-q) + 2.0f*p1;
    float e1, e2, e3;
    if (p2 < 1e-30f) {
        e1 = e2 = e3 = q;
    } else {
        float pp = sqrtf(p2 * (1.0f/6.0f));
        float inv = 1.0f / pp;
        float b00 = (m00 - q) * inv, b11 = (m11 - q) * inv, b22 = (m22 - q) * inv;
        float b01 = m01 * inv, b02 = m02 * inv, b12 = m12 * inv;
        float detB = b00 * (b11 * b22 - b12 * b12)
                   - b01 * (b01 * b22 - b12 * b02)
                   + b02 * (b01 * b12 - b11 * b02);
        float r = detB * 0.5f;
        r = fminf(1.0f, fmaxf(-1.0f, r));
        float phi = acosf(r) * (1.0f/3.0f);
        e1 = q + 2.0f * pp * cosf(phi);                       // largest
        e3 = q + 2.0f * pp * cosf(phi + 2.0943951023931953f); // smallest
        e2 = 3.0f * q - e1 - e3;
    }
    float s1 = sqrtf(fmaxf(e1, 0.f));
    float s2 = sqrtf(fmaxf(e2, 0.f));
    float s3 = sqrtf(fmaxf(e3, 0.f));
    float tr = s1 + s2 + ((detA >= 0.f) ? s3 : -s3);

    float msd = fmaxf(0.f, (Ep + Ec - 2.0f * tr) * invn);
    float r_out = sqrtf(msd);

    // block-reduce rmsd partial sum
    __shared__ float sm[K2_BLOCK / 32];
    const int lane = threadIdx.x & 31;
    const int wid  = threadIdx.x >> 5;
    float s = warp_sum(r_out);
    if (lane == 0) sm[wid] = s;
    __syncthreads();
    if (wid == 0) {
        float v = (lane < (K2_BLOCK / 32)) ? sm[lane] : 0.f;
        v = warp_sum(v);
        if (lane == 0) g_psum[blockIdx.x] = v;
    }
}

// ---------------- K3: final mean over partials ----------------
__global__ void mean_kernel(float* __restrict__ out)
{
    const int nparts = BATCHES / K2_BLOCK;   // 16
    float s = (threadIdx.x < nparts) ? g_psum[threadIdx.x] : 0.f;
    s = warp_sum(s);
    if (threadIdx.x == 0) out[0] = s / (float)BATCHES;
}

extern "C" void kernel_launch(void* const* d_in, const int* in_sizes, int n_in,
                              void* d_out, int out_size)
{
    const float* p = (const float*)d_in[0];   // coords_pred [B, N, 3]
    const float* c = (const float*)d_in[1];   // coords      [B, N, 3]

    stream_kernel<<<NCTA, 256>>>(p, c);
    solve_kernel<<<BATCHES / K2_BLOCK, K2_BLOCK>>>();
    mean_kernel<<<1, 32>>>((float*)d_out);
}